// round 14
// baseline (speedup 1.0000x reference)
#include <cuda_runtime.h>
#include <cuda_fp16.h>
#include <mma.h>
#include <cstdint>
#include <cfloat>

using namespace nvcuda;

#define B_   256
#define P_   128
#define K_   512
#define HID_ 64
#define EMB_ 1536   // K_ + 1024 (frame)

#define NATTN 256
#define NCONV 16
#define NQF   32
#define NTOT  (NATTN + NCONV + NQF)   // 304

// ---------------- device scratch ----------------
__device__ float g_qfp[16][B_][HID_];   // qf partials [d-slice][batch][h]
__device__ __half g_Bf[K_ * HID_];      // W1k as fp16, row-major [k][h]
__device__ int g_conv_done = 0;
__device__ int g_qf_done   = 0;
__device__ int g_attn_done = 0;

// ---------------- helpers ----------------
__device__ __forceinline__ uint32_t smem_u32(const void* p) {
    uint32_t a;
    asm("{ .reg .u64 t; cvta.to.shared.u64 t, %1; cvt.u32.u64 %0, t; }" : "=r"(a) : "l"(p));
    return a;
}
__device__ __forceinline__ void cp_async16(uint32_t dst, const void* src) {
    asm volatile("cp.async.cg.shared.global [%0], [%1], 16;" :: "r"(dst), "l"(src) : "memory");
}
#define CP_COMMIT()  asm volatile("cp.async.commit_group;" ::: "memory")
#define CP_WAIT(n)   asm volatile("cp.async.wait_group %0;" :: "n"(n) : "memory")

__device__ __forceinline__ void spin_until(const int* ctr, int target) {
    int v;
    do {
        asm volatile("ld.global.acquire.gpu.s32 %0, [%1];" : "=r"(v) : "l"(ctr) : "memory");
        if (v < target) __nanosleep(64);
    } while (v < target);
}

union PackH4 { __half h[4]; uint2 u; };

// ---------------- SMEM layout ----------------
// attn role:
//   [0)      sA : 2 x 128 x 72 half = 36864  } sH (128x68 f32) aliases [0,34816)
//   [36864)  sB : 3 x 64 x 72 half = 27648
//   [64512)  sQF 64f | [64768) sW2 64f | [65024) sScore 128f
//   [65536)  sCtx : 1024 f32 = 4096
// qf role: sWt [64][132] f32 = 33792 at [0) ; sX [32][128] f32 = 16384 at [33792)
#define OFF_A   0u
#define ABUF    18432u
#define OFF_B   36864u
#define BBUF    9216u
#define OFF_QF  64512u
#define OFF_W2  64768u
#define OFF_SC  65024u
#define OFF_CTX 65536u
#define SMEM_BYTES 69632
#define LDA 72
#define LDB 72
#define LDH 68
#define LDW 132

__global__ __launch_bounds__(256, 2)
void fused_all(const float* __restrict__ query,
               const float* __restrict__ keys,
               const float* __restrict__ frame,
               const int*   __restrict__ mask,
               const float* __restrict__ W1,
               const float* __restrict__ W2,
               float* __restrict__ out) {
    extern __shared__ char smem[];
    const int bid = blockIdx.x;
    const int t   = threadIdx.x;

    // ============ role: W1k -> fp16 converters (blocks 256..271) ============
    if (bid >= NATTN && bid < NATTN + NCONV) {
        const int base = (bid - NATTN) * 2048 + t * 8;
        PackH4 p[2];
        #pragma unroll
        for (int v = 0; v < 2; v++) {
            float4 x = *(const float4*)(W1 + base + v * 4);
            p[v].h[0] = __float2half_rn(x.x);
            p[v].h[1] = __float2half_rn(x.y);
            p[v].h[2] = __float2half_rn(x.z);
            p[v].h[3] = __float2half_rn(x.w);
        }
        *(uint4*)(g_Bf + base) = make_uint4(p[0].u.x, p[0].u.y, p[1].u.x, p[1].u.y);
        __threadfence();
        __syncthreads();
        if (t == 0) atomicAdd(&g_conv_done, 1);
        return;
    }

    // ============ role: qf tile-GEMMs (blocks 272..303) ============
    if (bid >= NATTN + NCONV) {
        float* sWt = (float*)smem;                  // [64][132]
        float* sX  = (float*)(smem + 33792);        // [32][128]
        const int qb = bid - (NATTN + NCONV);
        const int ds = qb >> 1;                      // 0..15 (128-dim slice)
        const int bg = qb & 1;                       // 0..1 (128 batches each)

        // stage Wt transposed: sWt[h][d] = W1[(K+ds*128+d)*64 + h]
        {
            const float4* wsrc = (const float4*)(W1 + (size_t)(K_ + ds * 128) * HID_);
            #pragma unroll
            for (int j = 0; j < 8; j++) {
                int idx = j * 256 + t;              // 0..2047
                int d  = idx >> 4;                  // 0..127
                int h4 = idx & 15;
                float4 v = wsrc[idx];
                sWt[(h4 * 4 + 0) * LDW + d] = v.x;
                sWt[(h4 * 4 + 1) * LDW + d] = v.y;
                sWt[(h4 * 4 + 2) * LDW + d] = v.z;
                sWt[(h4 * 4 + 3) * LDW + d] = v.w;
            }
        }
        const float* src = (ds < 8) ? (query + ds * 128) : (frame + (ds - 8) * 128);
        const int h  = t & 63;
        const int bq = t >> 6;                       // 0..3 -> 8 batches each

        for (int c = 0; c < 4; c++) {
            __syncthreads();                         // sX free (iter0: Wt staged)
            #pragma unroll
            for (int j = 0; j < 4; j++) {
                int idx = j * 256 + t;               // 0..1023
                int row = idx >> 5, c4 = idx & 31;
                *(float4*)(sX + row * 128 + c4 * 4) =
                    *(const float4*)(src + (size_t)(bg * 128 + c * 32 + row) * 1024 + c4 * 4);
            }
            __syncthreads();

            float acc[8] = {0.f,0.f,0.f,0.f,0.f,0.f,0.f,0.f};
            #pragma unroll 4
            for (int d = 0; d < 128; d += 4) {
                float4 wv = *(const float4*)(sWt + h * LDW + d);     // conflict-free LDS.128
                #pragma unroll
                for (int i = 0; i < 8; i++) {
                    float4 xv = *(const float4*)(sX + (bq * 8 + i) * 128 + d);  // warp-broadcast
                    acc[i] = fmaf(wv.x, xv.x, acc[i]);
                    acc[i] = fmaf(wv.y, xv.y, acc[i]);
                    acc[i] = fmaf(wv.z, xv.z, acc[i]);
                    acc[i] = fmaf(wv.w, xv.w, acc[i]);
                }
            }
            #pragma unroll
            for (int i = 0; i < 8; i++)
                g_qfp[ds][bg * 128 + c * 32 + bq * 8 + i][h] = acc[i];
        }
        __threadfence();
        __syncthreads();
        if (t == 0) atomicAdd(&g_qf_done, 1);
        return;
    }

    // ============ role: attention (blocks 0..255) ============
    const uint32_t sb = smem_u32(smem);
    float* sQF    = (float*)(smem + OFF_QF);
    float* sW2    = (float*)(smem + OFF_W2);
    float* sScore = (float*)(smem + OFF_SC);
    float* sCtx   = (float*)(smem + OFF_CTX);
    float* sH     = (float*)(smem + OFF_A);   // alias after GEMM

    const int b = bid;
    const int wid = t >> 5;
    const float* keyb = keys  + (size_t)b * P_ * K_;
    const float* fb   = frame + (size_t)b * 1024;

    const int arow = t >> 4;
    const int ac4  = t & 15;
    const int brow = t >> 3;
    const int bc8  = t & 7;

    // ---- prologue: A chunk 0 LDG first, spin on conv gate while it flies ----
    float4 ra[8];
    #pragma unroll
    for (int i = 0; i < 8; i++)
        ra[i] = *(const float4*)(keyb + (size_t)(arow + 16 * i) * K_ + ac4 * 4);

    if (t < HID_) sW2[t] = W2[t];

    if (t == 0) spin_until(&g_conv_done, NCONV);   // LDGs in flight meanwhile
    __syncthreads();

    #pragma unroll
    for (int i = 0; i < 2; i++) {
        int row = brow + 32 * i;
        cp_async16(sb + OFF_B + (uint32_t)(row * (LDB * 2) + bc8 * 16),
                   g_Bf + row * HID_ + bc8 * 8);
    }
    CP_COMMIT();
    #pragma unroll
    for (int i = 0; i < 2; i++) {
        int row = brow + 32 * i;
        cp_async16(sb + OFF_B + BBUF + (uint32_t)(row * (LDB * 2) + bc8 * 16),
                   g_Bf + 64 * HID_ + row * HID_ + bc8 * 8);
    }
    CP_COMMIT();

    {
        __half* sA0 = (__half*)(smem + OFF_A);
        #pragma unroll
        for (int i = 0; i < 8; i++) {
            PackH4 p;
            p.h[0] = __float2half_rn(ra[i].x);
            p.h[1] = __float2half_rn(ra[i].y);
            p.h[2] = __float2half_rn(ra[i].z);
            p.h[3] = __float2half_rn(ra[i].w);
            *(uint2*)(sA0 + (arow + 16 * i) * LDA + ac4 * 4) = p.u;
        }
    }
    #pragma unroll
    for (int i = 0; i < 8; i++)
        ra[i] = *(const float4*)(keyb + (size_t)(arow + 16 * i) * K_ + 64 + ac4 * 4);

    CP_WAIT(1);
    __syncthreads();

    // ---- GEMM mainloop: 1 barrier/chunk, B triple-buffered ----
    const int wm = wid & 3;
    const int wn = wid >> 2;
    wmma::fragment<wmma::accumulator, 16, 16, 16, float> acc[2][2];
    #pragma unroll
    for (int i = 0; i < 2; i++)
        #pragma unroll
        for (int j = 0; j < 2; j++) wmma::fill_fragment(acc[i][j], 0.f);

    #pragma unroll
    for (int kc = 0; kc < 8; kc++) {
        if (kc < 7) {
            __half* sAn = (__half*)(smem + OFF_A + ((kc + 1) & 1) * ABUF);
            #pragma unroll
            for (int i = 0; i < 8; i++) {
                PackH4 p;
                p.h[0] = __float2half_rn(ra[i].x);
                p.h[1] = __float2half_rn(ra[i].y);
                p.h[2] = __float2half_rn(ra[i].z);
                p.h[3] = __float2half_rn(ra[i].w);
                *(uint2*)(sAn + (arow + 16 * i) * LDA + ac4 * 4) = p.u;
            }
        }
        if (kc < 6) {
            #pragma unroll
            for (int i = 0; i < 8; i++)
                ra[i] = *(const float4*)(keyb + (size_t)(arow + 16 * i) * K_ + (kc + 2) * 64 + ac4 * 4);
        }
        if (kc < 6) {
            const uint32_t nb = OFF_B + (uint32_t)(((kc + 2) % 3)) * BBUF;
            #pragma unroll
            for (int i = 0; i < 2; i++) {
                int row = brow + 32 * i;
                cp_async16(sb + nb + (uint32_t)(row * (LDB * 2) + bc8 * 16),
                           g_Bf + (kc + 2) * 64 * HID_ + row * HID_ + bc8 * 8);
            }
            CP_COMMIT();
        }

        const __half* sA = (const __half*)(smem + OFF_A + (kc & 1) * ABUF);
        const __half* sB = (const __half*)(smem + OFF_B + (kc % 3) * BBUF);
        #pragma unroll
        for (int ks = 0; ks < 4; ks++) {
            wmma::fragment<wmma::matrix_a, 16, 16, 16, __half, wmma::row_major> a[2];
            #pragma unroll
            for (int i = 0; i < 2; i++)
                wmma::load_matrix_sync(a[i], sA + (wm * 32 + i * 16) * LDA + ks * 16, LDA);
            #pragma unroll
            for (int nf = 0; nf < 2; nf++) {
                wmma::fragment<wmma::matrix_b, 16, 16, 16, __half, wmma::row_major> bf;
                wmma::load_matrix_sync(bf, sB + (ks * 16) * LDB + wn * 32 + nf * 16, LDB);
                #pragma unroll
                for (int i = 0; i < 2; i++)
                    wmma::mma_sync(acc[i][nf], a[i], bf, acc[i][nf]);
            }
        }

        if (kc < 6) CP_WAIT(1);
        __syncthreads();
    }

    #pragma unroll
    for (int i = 0; i < 2; i++)
        #pragma unroll
        for (int j = 0; j < 2; j++)
            wmma::store_matrix_sync(sH + (wm * 32 + i * 16) * LDH + wn * 32 + j * 16,
                                    acc[i][j], LDH, wmma::mem_row_major);

    // gate: qf partials ready (producers ran during the ~16us mainloop)
    if (t == 0) spin_until(&g_qf_done, NQF);
    __syncthreads();

    if (t < HID_) {
        float s = 0.f;
        #pragma unroll
        for (int ds = 0; ds < 16; ds++) s += g_qfp[ds][b][t];
        sQF[t] = s;
    }
    __syncthreads();

    // ---- scores: relu(H + qf) . W2 ----
    if (t < P_) {
        float sc = 0.f;
        const float* hr = sH + t * LDH;
        #pragma unroll
        for (int j = 0; j < HID_; j++) {
            float hv = hr[j] + sQF[j];
            sc = fmaf(fmaxf(hv, 0.f), sW2[j], sc);
        }
        sScore[t] = sc;
    }
    __syncthreads();

    // ---- masked softmax ----
    if (t < 32) {
        int   mk[4];
        float scv[4], e[4];
        float mx = -FLT_MAX;
        #pragma unroll
        for (int i = 0; i < 4; i++) {
            int p = t + 32 * i;
            mk[i]  = mask[b * P_ + p];
            scv[i] = sScore[p];
            if (mk[i]) mx = fmaxf(mx, scv[i]);
        }
        #pragma unroll
        for (int off = 16; off >= 1; off >>= 1)
            mx = fmaxf(mx, __shfl_xor_sync(0xffffffffu, mx, off));
        float sum = 0.f;
        #pragma unroll
        for (int i = 0; i < 4; i++) { e[i] = mk[i] ? __expf(scv[i] - mx) : 0.f; sum += e[i]; }
        #pragma unroll
        for (int off = 16; off >= 1; off >>= 1)
            sum += __shfl_xor_sync(0xffffffffu, sum, off);
        float inv = 1.0f / sum;
        #pragma unroll
        for (int i = 0; i < 4; i++) {
            int p = t + 32 * i;
            float w = e[i] * inv;
            sScore[p] = w;
            out[(size_t)B_ * EMB_ + (size_t)b * P_ + p] = w;
        }
    }
    __syncthreads();

    // ---- context, vectorized split-p ----
    {
        const int th = t & 127;
        const int ph = (t >> 7) * 64;
        const float* kp = keyb + (size_t)ph * K_ + th * 4;
        float4 cacc = make_float4(0.f, 0.f, 0.f, 0.f);
        #pragma unroll 8
        for (int p = 0; p < 64; p++) {
            float w = sScore[ph + p];
            float4 kv = *(const float4*)(kp + (size_t)p * K_);
            cacc.x = fmaf(w, kv.x, cacc.x);
            cacc.y = fmaf(w, kv.y, cacc.y);
            cacc.z = fmaf(w, kv.z, cacc.z);
            cacc.w = fmaf(w, kv.w, cacc.w);
        }
        *(float4*)(sCtx + (t >> 7) * 512 + th * 4) = cacc;
    }
    __syncthreads();
    {
        float* eb = out + (size_t)b * EMB_;
        if (t < 128) {
            float4 a = *(const float4*)(sCtx + t * 4);
            float4 c = *(const float4*)(sCtx + 512 + t * 4);
            a.x += c.x; a.y += c.y; a.z += c.z; a.w += c.w;
            *(float4*)(eb + t * 4) = a;
        }
        #pragma unroll
        for (int i = 0; i < 4; i++)
            eb[K_ + t + 256 * i] = fb[t + 256 * i];
    }

    // ---- counter reset for graph replay determinism ----
    __syncthreads();
    if (t == 0) {
        int old = atomicAdd(&g_attn_done, 1);
        if (old == NATTN - 1) {
            g_conv_done = 0;
            g_qf_done   = 0;
            g_attn_done = 0;
            __threadfence();
        }
    }
}

extern "C" void kernel_launch(void* const* d_in, const int* in_sizes, int n_in,
                              void* d_out, int out_size) {
    const float* query = (const float*)d_in[0];
    const float* keys  = (const float*)d_in[1];
    const float* frame = (const float*)d_in[2];
    const int*   mask  = (const int*)d_in[3];
    const float* W1    = (const float*)d_in[4];
    const float* W2    = (const float*)d_in[5];
    float* out = (float*)d_out;

    static int cfg_done = 0;
    if (!cfg_done) {
        cudaFuncSetAttribute(fused_all, cudaFuncAttributeMaxDynamicSharedMemorySize, SMEM_BYTES);
        cfg_done = 1;
    }

    fused_all<<<NTOT, 256, SMEM_BYTES>>>(query, keys, frame, mask, W1, W2, out);
}

// round 16
// speedup vs baseline: 1.1995x; 1.1995x over previous
#include <cuda_runtime.h>
#include <cuda_fp16.h>
#include <mma.h>
#include <cstdint>
#include <cfloat>

using namespace nvcuda;

#define B_   256
#define P_   128
#define K_   512
#define HID_ 64
#define EMB_ 1536   // K_ + 1024 (frame)

// ---------------- device scratch ----------------
__device__ float g_qfp[16][B_][HID_];   // qf partials [d-slice][batch][h]
__device__ __half g_Bf[K_ * HID_];      // W1k as fp16, row-major [k][h]

// ---------------- helpers ----------------
__device__ __forceinline__ uint32_t smem_u32(const void* p) {
    uint32_t a;
    asm("{ .reg .u64 t; cvta.to.shared.u64 t, %1; cvt.u32.u64 %0, t; }" : "=r"(a) : "l"(p));
    return a;
}
__device__ __forceinline__ void cp_async16(uint32_t dst, const void* src) {
    asm volatile("cp.async.cg.shared.global [%0], [%1], 16;" :: "r"(dst), "l"(src) : "memory");
}
#define CP_COMMIT()  asm volatile("cp.async.commit_group;" ::: "memory")
#define CP_WAIT(n)   asm volatile("cp.async.wait_group %0;" :: "n"(n) : "memory")

union PackH4 { __half h[4]; uint2 u; };

// ---------------- kernel 1: qf partials (512) + W1k fp16 convert (16) ----------------
__global__ __launch_bounds__(256, 4)
void qf_kernel(const float* __restrict__ query,
               const float* __restrict__ frame,
               const float* __restrict__ W1) {
    if (blockIdx.x >= 512) {
        const int base = (blockIdx.x - 512) * 2048 + threadIdx.x * 8;
        PackH4 p[2];
        #pragma unroll
        for (int v = 0; v < 2; v++) {
            float4 x = *(const float4*)(W1 + base + v * 4);
            p[v].h[0] = __float2half_rn(x.x);
            p[v].h[1] = __float2half_rn(x.y);
            p[v].h[2] = __float2half_rn(x.z);
            p[v].h[3] = __float2half_rn(x.w);
        }
        *(uint4*)(g_Bf + base) = make_uint4(p[0].u.x, p[0].u.y, p[1].u.x, p[1].u.y);
        return;
    }
    __shared__ float sX[8][128];
    const int bg = blockIdx.x & 31;
    const int ds = blockIdx.x >> 5;
    const int t  = threadIdx.x;

    const float* src = (ds < 8) ? (query + ds * 128) : (frame + (ds - 8) * 128);
    #pragma unroll
    for (int j = 0; j < 4; j++) {
        int lin = j * 256 + t;
        int bb = lin >> 7, ff = lin & 127;
        sX[bb][ff] = src[(size_t)(bg * 8 + bb) * 1024 + ff];
    }
    __syncthreads();

    const int h  = t & 63;
    const int bs = t >> 6;
    const float* w = W1 + (size_t)(K_ + ds * 128) * HID_ + h;
    float a0 = 0.f, a1 = 0.f;
    #pragma unroll 8
    for (int d = 0; d < 128; d++) {
        float wv = w[(size_t)d * HID_];
        a0 = fmaf(wv, sX[bs][d],     a0);
        a1 = fmaf(wv, sX[bs + 4][d], a1);
    }
    g_qfp[ds][bg * 8 + bs][h]     = a0;
    g_qfp[ds][bg * 8 + bs + 4][h] = a1;
}

// ---------------- kernel 2: main attention with mask compaction ----------------
// SMEM (bytes):
//   [0)      sA : 2 x 128 x 72 half = 36864  } sH (128x68 f32) aliases [0,34816)
//   [36864)  sB : 3 x 64 x 72 half = 27648
//   [64512)  sQF 64f | [64768) sW2 64f
//   [65024)  sSCC 128f (compact scores->weights)
//   [65536)  sSCF 128f (full-layout weights)
//   [66048)  sPidx 128 int
//   [66560)  sMisc 16 int (warp sums, Pm)
//   [66624)  sCtx 1024 f32
#define OFF_A    0u
#define ABUF     18432u
#define OFF_B    36864u
#define BBUF     9216u
#define OFF_QF   64512u
#define OFF_W2   64768u
#define OFF_SCC  65024u
#define OFF_SCF  65536u
#define OFF_PIDX 66048u
#define OFF_MISC 66560u
#define OFF_CTX  66624u
#define SMEM_BYTES 70720
#define LDA 72
#define LDB 72
#define LDH 68

__global__ __launch_bounds__(256, 2)
void attn_main(const float* __restrict__ keys,
               const float* __restrict__ frame,
               const int*   __restrict__ mask,
               const float* __restrict__ W2,
               float* __restrict__ out) {
    extern __shared__ char smem[];
    const uint32_t sb = smem_u32(smem);
    float* sQF   = (float*)(smem + OFF_QF);
    float* sW2   = (float*)(smem + OFF_W2);
    float* sSCC  = (float*)(smem + OFF_SCC);
    float* sSCF  = (float*)(smem + OFF_SCF);
    int*   sPidx = (int*)  (smem + OFF_PIDX);
    int*   sMisc = (int*)  (smem + OFF_MISC);
    float* sCtx  = (float*)(smem + OFF_CTX);
    float* sH    = (float*)(smem + OFF_A);   // alias after GEMM

    const int b = blockIdx.x;
    const int t = threadIdx.x;
    const int wid = t >> 5;
    const float* keyb = keys  + (size_t)b * P_ * K_;
    const float* fb   = frame + (size_t)b * 1024;

    const int arow = t >> 4;
    const int ac4  = t & 15;
    const int brow = t >> 3;
    const int bc8  = t & 7;

    // ---- mask compaction (ballot scan over 128 entries) ----
    int m = 0;
    unsigned bal = 0;
    if (t < 128) {
        m = mask[b * P_ + t];
        bal = __ballot_sync(0xffffffffu, m != 0);
        if ((t & 31) == 0) sMisc[t >> 5] = __popc(bal);
    }
    if (t < HID_) {
        float s = 0.f;
        #pragma unroll
        for (int ds = 0; ds < 16; ds++) s += g_qfp[ds][b][t];
        sQF[t] = s;
        sW2[t] = W2[t];
    }
    __syncthreads();
    if (t < 128 && m) {
        int wi = t >> 5;
        int base = 0;
        #pragma unroll
        for (int k = 0; k < 4; k++) if (k < wi) base += sMisc[k];
        sPidx[base + __popc(bal & ((1u << (t & 31)) - 1u))] = t;
    }
    if (t == 0) sMisc[4] = sMisc[0] + sMisc[1] + sMisc[2] + sMisc[3];
    __syncthreads();
    const int Pm    = sMisc[4];               // >= 1 (mask[:,0]==1)
    const int PmPad = ((Pm + 31) >> 5) << 5;  // 32..128
    const bool wact = (((t >> 5) & 3) * 32) < PmPad;   // warp M-tile active

    // per-thread compacted source rows for the 8 A-row slots (packed 8b each)
    uint32_t gpk0 = 0, gpk1 = 0;
    #pragma unroll
    for (int i = 0; i < 8; i++) {
        int row = arow + 16 * i;
        int gp = sPidx[row < Pm ? row : (Pm - 1)];
        if (i < 4) gpk0 |= (uint32_t)gp << (i * 8);
        else       gpk1 |= (uint32_t)gp << ((i - 4) * 8);
    }
    #define GPROW(i) ((int)(((i) < 4 ? (gpk0 >> ((i) * 8)) : (gpk1 >> (((i) - 4) * 8))) & 255u))

    // ---- prologue ----
    float4 ra[8];
    #pragma unroll
    for (int i = 0; i < 8; i++)
        if (arow + 16 * i < PmPad)
            ra[i] = *(const float4*)(keyb + (size_t)GPROW(i) * K_ + ac4 * 4);
    #pragma unroll
    for (int i = 0; i < 2; i++) {
        int row = brow + 32 * i;
        cp_async16(sb + OFF_B + (uint32_t)(row * (LDB * 2) + bc8 * 16),
                   g_Bf + row * HID_ + bc8 * 8);
    }
    CP_COMMIT();
    #pragma unroll
    for (int i = 0; i < 2; i++) {
        int row = brow + 32 * i;
        cp_async16(sb + OFF_B + BBUF + (uint32_t)(row * (LDB * 2) + bc8 * 16),
                   g_Bf + 64 * HID_ + row * HID_ + bc8 * 8);
    }
    CP_COMMIT();

    {
        __half* sA0 = (__half*)(smem + OFF_A);
        #pragma unroll
        for (int i = 0; i < 8; i++) {
            if (arow + 16 * i < PmPad) {
                PackH4 p;
                p.h[0] = __float2half_rn(ra[i].x);
                p.h[1] = __float2half_rn(ra[i].y);
                p.h[2] = __float2half_rn(ra[i].z);
                p.h[3] = __float2half_rn(ra[i].w);
                *(uint2*)(sA0 + (arow + 16 * i) * LDA + ac4 * 4) = p.u;
            }
        }
    }
    #pragma unroll
    for (int i = 0; i < 8; i++)
        if (arow + 16 * i < PmPad)
            ra[i] = *(const float4*)(keyb + (size_t)GPROW(i) * K_ + 64 + ac4 * 4);

    CP_WAIT(1);
    __syncthreads();

    // ---- GEMM mainloop: 1 barrier/chunk, B triple-buffered, M predicated ----
    const int wm = wid & 3;
    const int wn = wid >> 2;
    wmma::fragment<wmma::accumulator, 16, 16, 16, float> acc[2][2];
    #pragma unroll
    for (int i = 0; i < 2; i++)
        #pragma unroll
        for (int j = 0; j < 2; j++) wmma::fill_fragment(acc[i][j], 0.f);

    #pragma unroll
    for (int kc = 0; kc < 8; kc++) {
        if (kc < 7) {
            __half* sAn = (__half*)(smem + OFF_A + ((kc + 1) & 1) * ABUF);
            #pragma unroll
            for (int i = 0; i < 8; i++) {
                if (arow + 16 * i < PmPad) {
                    PackH4 p;
                    p.h[0] = __float2half_rn(ra[i].x);
                    p.h[1] = __float2half_rn(ra[i].y);
                    p.h[2] = __float2half_rn(ra[i].z);
                    p.h[3] = __float2half_rn(ra[i].w);
                    *(uint2*)(sAn + (arow + 16 * i) * LDA + ac4 * 4) = p.u;
                }
            }
        }
        if (kc < 6) {
            #pragma unroll
            for (int i = 0; i < 8; i++)
                if (arow + 16 * i < PmPad)
                    ra[i] = *(const float4*)(keyb + (size_t)GPROW(i) * K_ + (kc + 2) * 64 + ac4 * 4);
        }
        if (kc < 6) {
            const uint32_t nb = OFF_B + (uint32_t)(((kc + 2) % 3)) * BBUF;
            #pragma unroll
            for (int i = 0; i < 2; i++) {
                int row = brow + 32 * i;
                cp_async16(sb + nb + (uint32_t)(row * (LDB * 2) + bc8 * 16),
                           g_Bf + (kc + 2) * 64 * HID_ + row * HID_ + bc8 * 8);
            }
            CP_COMMIT();
        }

        if (wact) {
            const __half* sA = (const __half*)(smem + OFF_A + (kc & 1) * ABUF);
            const __half* sB = (const __half*)(smem + OFF_B + (kc % 3) * BBUF);
            #pragma unroll
            for (int ks = 0; ks < 4; ks++) {
                wmma::fragment<wmma::matrix_a, 16, 16, 16, __half, wmma::row_major> a[2];
                #pragma unroll
                for (int i = 0; i < 2; i++)
                    wmma::load_matrix_sync(a[i], sA + (wm * 32 + i * 16) * LDA + ks * 16, LDA);
                #pragma unroll
                for (int nf = 0; nf < 2; nf++) {
                    wmma::fragment<wmma::matrix_b, 16, 16, 16, __half, wmma::row_major> bf;
                    wmma::load_matrix_sync(bf, sB + (ks * 16) * LDB + wn * 32 + nf * 16, LDB);
                    #pragma unroll
                    for (int i = 0; i < 2; i++)
                        wmma::mma_sync(acc[i][nf], a[i], bf, acc[i][nf]);
                }
            }
        }

        if (kc < 6) CP_WAIT(1);
        __syncthreads();
    }

    if (wact) {
        #pragma unroll
        for (int i = 0; i < 2; i++)
            #pragma unroll
            for (int j = 0; j < 2; j++)
                wmma::store_matrix_sync(sH + (wm * 32 + i * 16) * LDH + wn * 32 + j * 16,
                                        acc[i][j], LDH, wmma::mem_row_major);
    }
    __syncthreads();

    // ---- scores for compact rows ----
    if (t < Pm) {
        float sc = 0.f;
        const float* hr = sH + t * LDH;
        #pragma unroll
        for (int j = 0; j < HID_; j++) {
            float hv = hr[j] + sQF[j];
            sc = fmaf(fmaxf(hv, 0.f), sW2[j], sc);
        }
        sSCC[t] = sc;
    }
    if (t < 128) sSCF[t] = 0.f;
    __syncthreads();

    // ---- softmax over the compact list (all entries unmasked) ----
    if (t < 32) {
        float scv[4], e[4];
        float mx = -FLT_MAX;
        #pragma unroll
        for (int i = 0; i < 4; i++) {
            int j = t + 32 * i;
            scv[i] = (j < Pm) ? sSCC[j] : -FLT_MAX;
            mx = fmaxf(mx, scv[i]);
        }
        #pragma unroll
        for (int off = 16; off >= 1; off >>= 1)
            mx = fmaxf(mx, __shfl_xor_sync(0xffffffffu, mx, off));
        float sum = 0.f;
        #pragma unroll
        for (int i = 0; i < 4; i++) {
            int j = t + 32 * i;
            e[i] = (j < Pm) ? __expf(scv[i] - mx) : 0.f;
            sum += e[i];
        }
        #pragma unroll
        for (int off = 16; off >= 1; off >>= 1)
            sum += __shfl_xor_sync(0xffffffffu, sum, off);
        float inv = 1.0f / sum;
        #pragma unroll
        for (int i = 0; i < 4; i++) {
            int j = t + 32 * i;
            if (j < Pm) sSCC[j] = e[i] * inv;   // compact weights
        }
    }
    __syncthreads();

    // scatter weights to full layout; write weights output
    if (t < Pm) sSCF[sPidx[t]] = sSCC[t];
    __syncthreads();
    if (t < 128) out[(size_t)B_ * EMB_ + (size_t)b * P_ + t] = sSCF[t];

    // ---- context over compact rows only ----
    {
        const int g  = t >> 7;
        const int th = t & 127;
        const int half = (Pm + 1) >> 1;
        const int j0 = g * half;
        const int j1 = (g == 0) ? half : Pm;
        float4 cacc = make_float4(0.f, 0.f, 0.f, 0.f);
        #pragma unroll 4
        for (int j = j0; j < j1; j++) {
            float w = sSCC[j];
            int gp = sPidx[j];
            float4 kv = *(const float4*)(keyb + (size_t)gp * K_ + th * 4);
            cacc.x = fmaf(w, kv.x, cacc.x);
            cacc.y = fmaf(w, kv.y, cacc.y);
            cacc.z = fmaf(w, kv.z, cacc.z);
            cacc.w = fmaf(w, kv.w, cacc.w);
        }
        *(float4*)(sCtx + g * 512 + th * 4) = cacc;
    }
    __syncthreads();
    {
        float* eb = out + (size_t)b * EMB_;
        if (t < 128) {
            float4 a = *(const float4*)(sCtx + t * 4);
            float4 c = *(const float4*)(sCtx + 512 + t * 4);
            a.x += c.x; a.y += c.y; a.z += c.z; a.w += c.w;
            *(float4*)(eb + t * 4) = a;
        }
        #pragma unroll
        for (int i = 0; i < 4; i++)
            eb[K_ + t + 256 * i] = fb[t + 256 * i];
    }
}

extern "C" void kernel_launch(void* const* d_in, const int* in_sizes, int n_in,
                              void* d_out, int out_size) {
    const float* query = (const float*)d_in[0];
    const float* keys  = (const float*)d_in[1];
    const float* frame = (const float*)d_in[2];
    const int*   mask  = (const int*)d_in[3];
    const float* W1    = (const float*)d_in[4];
    const float* W2    = (const float*)d_in[5];
    float* out = (float*)d_out;

    static int cfg_done = 0;
    if (!cfg_done) {
        cudaFuncSetAttribute(attn_main, cudaFuncAttributeMaxDynamicSharedMemorySize, SMEM_BYTES);
        cfg_done = 1;
    }

    qf_kernel<<<528, 256>>>(query, frame, W1);
    attn_main<<<B_, 256, SMEM_BYTES>>>(keys, frame, mask, W2, out);
}

// round 17
// speedup vs baseline: 1.2959x; 1.0804x over previous
#include <cuda_runtime.h>
#include <cuda_fp16.h>
#include <mma.h>
#include <cstdint>
#include <cfloat>

using namespace nvcuda;

#define B_   256
#define P_   128
#define K_   512
#define HID_ 64
#define EMB_ 1536   // K_ + 1024 (frame)

// ---------------- device scratch ----------------
__device__ float g_qfp[16][B_][HID_];   // qf partials [d-slice][batch][h]
__device__ __half g_Bf[K_ * HID_];      // W1k as fp16, row-major [k][h]

// ---------------- helpers ----------------
__device__ __forceinline__ uint32_t smem_u32(const void* p) {
    uint32_t a;
    asm("{ .reg .u64 t; cvta.to.shared.u64 t, %1; cvt.u32.u64 %0, t; }" : "=r"(a) : "l"(p));
    return a;
}
__device__ __forceinline__ void cp_async16(uint32_t dst, const void* src) {
    asm volatile("cp.async.cg.shared.global [%0], [%1], 16;" :: "r"(dst), "l"(src) : "memory");
}
#define CP_COMMIT()  asm volatile("cp.async.commit_group;" ::: "memory")
#define CP_WAIT(n)   asm volatile("cp.async.wait_group %0;" :: "n"(n) : "memory")

union PackH4 { __half h[4]; uint2 u; };

// ---------------- kernel 1: qf partials (512) + W1k fp16 convert (16) ----------------
__global__ __launch_bounds__(256, 4)
void qf_kernel(const float* __restrict__ query,
               const float* __restrict__ frame,
               const float* __restrict__ W1) {
    if (blockIdx.x >= 512) {
        const int base = (blockIdx.x - 512) * 2048 + threadIdx.x * 8;
        PackH4 p[2];
        #pragma unroll
        for (int v = 0; v < 2; v++) {
            float4 x = *(const float4*)(W1 + base + v * 4);
            p[v].h[0] = __float2half_rn(x.x);
            p[v].h[1] = __float2half_rn(x.y);
            p[v].h[2] = __float2half_rn(x.z);
            p[v].h[3] = __float2half_rn(x.w);
        }
        *(uint4*)(g_Bf + base) = make_uint4(p[0].u.x, p[0].u.y, p[1].u.x, p[1].u.y);
        return;
    }
    __shared__ float sX[8][128];
    const int bg = blockIdx.x & 31;
    const int ds = blockIdx.x >> 5;
    const int t  = threadIdx.x;

    const float* src = (ds < 8) ? (query + ds * 128) : (frame + (ds - 8) * 128);
    #pragma unroll
    for (int j = 0; j < 4; j++) {
        int lin = j * 256 + t;
        int bb = lin >> 7, ff = lin & 127;
        sX[bb][ff] = src[(size_t)(bg * 8 + bb) * 1024 + ff];
    }
    __syncthreads();

    const int h  = t & 63;
    const int bs = t >> 6;
    const float* w = W1 + (size_t)(K_ + ds * 128) * HID_ + h;
    float a0 = 0.f, a1 = 0.f;
    #pragma unroll 8
    for (int d = 0; d < 128; d++) {
        float wv = w[(size_t)d * HID_];
        a0 = fmaf(wv, sX[bs][d],     a0);
        a1 = fmaf(wv, sX[bs + 4][d], a1);
    }
    g_qfp[ds][bg * 8 + bs][h]     = a0;
    g_qfp[ds][bg * 8 + bs + 4][h] = a1;
}

// ---------------- kernel 2: main attention with mask compaction ----------------
// SMEM layout identical to R16.
#define OFF_A    0u
#define ABUF     18432u
#define OFF_B    36864u
#define BBUF     9216u
#define OFF_QF   64512u
#define OFF_W2   64768u
#define OFF_SCC  65024u
#define OFF_SCF  65536u
#define OFF_PIDX 66048u
#define OFF_MISC 66560u
#define OFF_CTX  66624u
#define SMEM_BYTES 70720
#define LDA 72
#define LDB 72
#define LDH 68

__global__ __launch_bounds__(256, 2)
void attn_main(const float* __restrict__ keys,
               const float* __restrict__ frame,
               const int*   __restrict__ mask,
               const float* __restrict__ W2,
               float* __restrict__ out) {
    extern __shared__ char smem[];
    const uint32_t sb = smem_u32(smem);
    float* sQF   = (float*)(smem + OFF_QF);
    float* sW2   = (float*)(smem + OFF_W2);
    float* sSCC  = (float*)(smem + OFF_SCC);
    float* sSCF  = (float*)(smem + OFF_SCF);
    int*   sPidx = (int*)  (smem + OFF_PIDX);
    int*   sMisc = (int*)  (smem + OFF_MISC);
    float* sCtx  = (float*)(smem + OFF_CTX);
    float* sH    = (float*)(smem + OFF_A);   // alias after GEMM

    const int b = blockIdx.x;
    const int t = threadIdx.x;
    const int wid = t >> 5;
    const float* keyb = keys  + (size_t)b * P_ * K_;
    const float* fb   = frame + (size_t)b * 1024;

    const int arow = t >> 4;
    const int ac4  = t & 15;
    const int brow = t >> 3;
    const int bc8  = t & 7;

    // ---- mask compaction ----
    int m = 0;
    unsigned bal = 0;
    if (t < 128) {
        m = mask[b * P_ + t];
        bal = __ballot_sync(0xffffffffu, m != 0);
        if ((t & 31) == 0) sMisc[t >> 5] = __popc(bal);
    }
    if (t < HID_) {
        float s = 0.f;
        #pragma unroll
        for (int ds = 0; ds < 16; ds++) s += g_qfp[ds][b][t];
        sQF[t] = s;
        sW2[t] = W2[t];
    }
    __syncthreads();
    if (t < 128 && m) {
        int wi = t >> 5;
        int base = 0;
        #pragma unroll
        for (int k = 0; k < 4; k++) if (k < wi) base += sMisc[k];
        sPidx[base + __popc(bal & ((1u << (t & 31)) - 1u))] = t;
    }
    if (t == 0) sMisc[4] = sMisc[0] + sMisc[1] + sMisc[2] + sMisc[3];
    __syncthreads();
    const int Pm    = sMisc[4];
    const int PmPad = ((Pm + 31) >> 5) << 5;
    // warp tiling: wm = wid>>1 so active warps are contiguous wids -> all 4 SMSPs busy
    const int wm = wid >> 1;
    const int wn = wid & 1;
    const bool wact = (wm * 32) < PmPad;

    uint32_t gpk0 = 0, gpk1 = 0;
    #pragma unroll
    for (int i = 0; i < 8; i++) {
        int row = arow + 16 * i;
        int gp = sPidx[row < Pm ? row : (Pm - 1)];
        if (i < 4) gpk0 |= (uint32_t)gp << (i * 8);
        else       gpk1 |= (uint32_t)gp << ((i - 4) * 8);
    }
    #define GPROW(i) ((int)(((i) < 4 ? (gpk0 >> ((i) * 8)) : (gpk1 >> (((i) - 4) * 8))) & 255u))

    // ---- prologue ----
    float4 ra[8];
    #pragma unroll
    for (int i = 0; i < 8; i++)
        if (arow + 16 * i < PmPad)
            ra[i] = *(const float4*)(keyb + (size_t)GPROW(i) * K_ + ac4 * 4);
    #pragma unroll
    for (int i = 0; i < 2; i++) {
        int row = brow + 32 * i;
        cp_async16(sb + OFF_B + (uint32_t)(row * (LDB * 2) + bc8 * 16),
                   g_Bf + row * HID_ + bc8 * 8);
    }
    CP_COMMIT();
    #pragma unroll
    for (int i = 0; i < 2; i++) {
        int row = brow + 32 * i;
        cp_async16(sb + OFF_B + BBUF + (uint32_t)(row * (LDB * 2) + bc8 * 16),
                   g_Bf + 64 * HID_ + row * HID_ + bc8 * 8);
    }
    CP_COMMIT();

    {
        __half* sA0 = (__half*)(smem + OFF_A);
        #pragma unroll
        for (int i = 0; i < 8; i++) {
            if (arow + 16 * i < PmPad) {
                PackH4 p;
                p.h[0] = __float2half_rn(ra[i].x);
                p.h[1] = __float2half_rn(ra[i].y);
                p.h[2] = __float2half_rn(ra[i].z);
                p.h[3] = __float2half_rn(ra[i].w);
                *(uint2*)(sA0 + (arow + 16 * i) * LDA + ac4 * 4) = p.u;
            }
        }
    }
    #pragma unroll
    for (int i = 0; i < 8; i++)
        if (arow + 16 * i < PmPad)
            ra[i] = *(const float4*)(keyb + (size_t)GPROW(i) * K_ + 64 + ac4 * 4);

    CP_WAIT(1);
    __syncthreads();

    // ---- GEMM mainloop ----
    wmma::fragment<wmma::accumulator, 16, 16, 16, float> acc[2][2];
    #pragma unroll
    for (int i = 0; i < 2; i++)
        #pragma unroll
        for (int j = 0; j < 2; j++) wmma::fill_fragment(acc[i][j], 0.f);

    #pragma unroll
    for (int kc = 0; kc < 8; kc++) {
        if (kc < 7) {
            __half* sAn = (__half*)(smem + OFF_A + ((kc + 1) & 1) * ABUF);
            #pragma unroll
            for (int i = 0; i < 8; i++) {
                if (arow + 16 * i < PmPad) {
                    PackH4 p;
                    p.h[0] = __float2half_rn(ra[i].x);
                    p.h[1] = __float2half_rn(ra[i].y);
                    p.h[2] = __float2half_rn(ra[i].z);
                    p.h[3] = __float2half_rn(ra[i].w);
                    *(uint2*)(sAn + (arow + 16 * i) * LDA + ac4 * 4) = p.u;
                }
            }
        }
        if (kc < 6) {
            #pragma unroll
            for (int i = 0; i < 8; i++)
                if (arow + 16 * i < PmPad)
                    ra[i] = *(const float4*)(keyb + (size_t)GPROW(i) * K_ + (kc + 2) * 64 + ac4 * 4);
        }
        if (kc < 6) {
            const uint32_t nb = OFF_B + (uint32_t)(((kc + 2) % 3)) * BBUF;
            #pragma unroll
            for (int i = 0; i < 2; i++) {
                int row = brow + 32 * i;
                cp_async16(sb + nb + (uint32_t)(row * (LDB * 2) + bc8 * 16),
                           g_Bf + (kc + 2) * 64 * HID_ + row * HID_ + bc8 * 8);
            }
            CP_COMMIT();
        }

        if (wact) {
            const __half* sA = (const __half*)(smem + OFF_A + (kc & 1) * ABUF);
            const __half* sB = (const __half*)(smem + OFF_B + (kc % 3) * BBUF);
            #pragma unroll
            for (int ks = 0; ks < 4; ks++) {
                wmma::fragment<wmma::matrix_a, 16, 16, 16, __half, wmma::row_major> a[2];
                #pragma unroll
                for (int i = 0; i < 2; i++)
                    wmma::load_matrix_sync(a[i], sA + (wm * 32 + i * 16) * LDA + ks * 16, LDA);
                #pragma unroll
                for (int nf = 0; nf < 2; nf++) {
                    wmma::fragment<wmma::matrix_b, 16, 16, 16, __half, wmma::row_major> bf;
                    wmma::load_matrix_sync(bf, sB + (ks * 16) * LDB + wn * 32 + nf * 16, LDB);
                    #pragma unroll
                    for (int i = 0; i < 2; i++)
                        wmma::mma_sync(acc[i][nf], a[i], bf, acc[i][nf]);
                }
            }
        }

        if (kc < 6) CP_WAIT(1);
        __syncthreads();
    }

    if (wact) {
        #pragma unroll
        for (int i = 0; i < 2; i++)
            #pragma unroll
            for (int j = 0; j < 2; j++)
                wmma::store_matrix_sync(sH + (wm * 32 + i * 16) * LDH + wn * 32 + j * 16,
                                        acc[i][j], LDH, wmma::mem_row_major);
    }
    __syncthreads();

    // ---- scores for compact rows ----
    if (t < Pm) {
        float sc = 0.f;
        const float* hr = sH + t * LDH;
        #pragma unroll
        for (int j = 0; j < HID_; j++) {
            float hv = hr[j] + sQF[j];
            sc = fmaf(fmaxf(hv, 0.f), sW2[j], sc);
        }
        sSCC[t] = sc;
    }
    if (t < 128) sSCF[t] = 0.f;
    __syncthreads();

    // ---- softmax over the compact list ----
    if (t < 32) {
        float scv[4], e[4];
        float mx = -FLT_MAX;
        #pragma unroll
        for (int i = 0; i < 4; i++) {
            int j = t + 32 * i;
            scv[i] = (j < Pm) ? sSCC[j] : -FLT_MAX;
            mx = fmaxf(mx, scv[i]);
        }
        #pragma unroll
        for (int off = 16; off >= 1; off >>= 1)
            mx = fmaxf(mx, __shfl_xor_sync(0xffffffffu, mx, off));
        float sum = 0.f;
        #pragma unroll
        for (int i = 0; i < 4; i++) {
            int j = t + 32 * i;
            e[i] = (j < Pm) ? __expf(scv[i] - mx) : 0.f;
            sum += e[i];
        }
        #pragma unroll
        for (int off = 16; off >= 1; off >>= 1)
            sum += __shfl_xor_sync(0xffffffffu, sum, off);
        float inv = 1.0f / sum;
        #pragma unroll
        for (int i = 0; i < 4; i++) {
            int j = t + 32 * i;
            if (j < Pm) sSCC[j] = e[i] * inv;
        }
    }
    __syncthreads();

    if (t < Pm) sSCF[sPidx[t]] = sSCC[t];
    __syncthreads();
    if (t < 128) out[(size_t)B_ * EMB_ + (size_t)b * P_ + t] = sSCF[t];

    // ---- context over compact rows only ----
    {
        const int g  = t >> 7;
        const int th = t & 127;
        const int half = (Pm + 1) >> 1;
        const int j0 = g * half;
        const int j1 = (g == 0) ? half : Pm;
        float4 cacc = make_float4(0.f, 0.f, 0.f, 0.f);
        #pragma unroll 4
        for (int j = j0; j < j1; j++) {
            float w = sSCC[j];
            int gp = sPidx[j];
            float4 kv = *(const float4*)(keyb + (size_t)gp * K_ + th * 4);
            cacc.x = fmaf(w, kv.x, cacc.x);
            cacc.y = fmaf(w, kv.y, cacc.y);
            cacc.z = fmaf(w, kv.z, cacc.z);
            cacc.w = fmaf(w, kv.w, cacc.w);
        }
        *(float4*)(sCtx + g * 512 + th * 4) = cacc;
    }
    __syncthreads();
    {
        float* eb = out + (size_t)b * EMB_;
        if (t < 128) {
            float4 a = *(const float4*)(sCtx + t * 4);
            float4 c = *(const float4*)(sCtx + 512 + t * 4);
            a.x += c.x; a.y += c.y; a.z += c.z; a.w += c.w;
            *(float4*)(eb + t * 4) = a;
        }
        #pragma unroll
        for (int i = 0; i < 4; i++)
            eb[K_ + t + 256 * i] = fb[t + 256 * i];
    }
}

extern "C" void kernel_launch(void* const* d_in, const int* in_sizes, int n_in,
                              void* d_out, int out_size) {
    const float* query = (const float*)d_in[0];
    const float* keys  = (const float*)d_in[1];
    const float* frame = (const float*)d_in[2];
    const int*   mask  = (const int*)d_in[3];
    const float* W1    = (const float*)d_in[4];
    const float* W2    = (const float*)d_in[5];
    float* out = (float*)d_out;

    static int cfg_done = 0;
    if (!cfg_done) {
        cudaFuncSetAttribute(attn_main, cudaFuncAttributeMaxDynamicSharedMemorySize, SMEM_BYTES);
        cfg_done = 1;
    }

    qf_kernel<<<528, 256>>>(query, frame, W1);
    attn_main<<<B_, 256, SMEM_BYTES>>>(keys, frame, mask, W2, out);
}